// round 14
// baseline (speedup 1.0000x reference)
#include <cuda_runtime.h>
#include <cuda_bf16.h>

#define Nq 32768
#define Mp 8192
#define C  128

// ---- norm-binned knn config ----
#define NB   256
#define BINV (NB/4.5f)
#define BW   (4.5f/NB)
#define CAPK 512            // staged candidate pairs per chunk (1024 cands)
#define FBIG 3.4e38f
#define MARG 1e-3f

typedef unsigned long long ull;

union F2U { float2 f; ull u; };
__device__ __forceinline__ ull pk2(float a, float b){ F2U t; t.f.x=a; t.f.y=b; return t.u; }
__device__ __forceinline__ float lo2(ull v){ F2U t; t.u=v; return t.f.x; }
__device__ __forceinline__ float hi2(ull v){ F2U t; t.u=v; return t.f.y; }
__device__ __forceinline__ ull fma2(ull a, ull b, ull c){
    ull d; asm("fma.rn.f32x2 %0, %1, %2, %3;" : "=l"(d) : "l"(a), "l"(b), "l"(c)); return d;
}

// stable top-3 insert, lexicographic (value, index): matches jax.lax.top_k tie
// semantics, independent of candidate visit order (R8-proven).
__device__ __forceinline__ void ins3i(float t, int idx,
                                      float& d0, float& d1, float& d2,
                                      int& i0, int& i1, int& i2)
{
    const bool b0 = (t < d0) || (t == d0 && idx < i0);
    const bool b1 = (t < d1) || (t == d1 && idx < i1);
    const bool b2 = (t < d2) || (t == d2 && idx < i2);
    d2 = b1 ? d1 : (b2 ? t : d2);
    i2 = b1 ? i1 : (b2 ? idx : i2);
    d1 = b0 ? d0 : (b1 ? t : d1);
    i1 = b0 ? i0 : (b1 ? idx : i1);
    d0 = b0 ? t : d0;
    i0 = b0 ? idx : i0;
}

__device__ __forceinline__ unsigned smem_to_u32(const void* p){
    unsigned a;
    asm("{ .reg .u64 tmp; cvta.to.shared.u64 tmp, %1; cvt.u32.u64 %0, tmp; }" : "=r"(a) : "l"(p));
    return a;
}

#define LDSM_X4(r, addr) \
    asm volatile("ldmatrix.sync.aligned.m8n8.x4.shared.b16 {%0,%1,%2,%3}, [%4];" \
        : "=r"((r)[0]),"=r"((r)[1]),"=r"((r)[2]),"=r"((r)[3]) : "r"(addr))

#define MMA16816(d, a, b0_, b1_) \
    asm volatile("mma.sync.aligned.m16n8k16.row.col.f32.bf16.bf16.f32 " \
        "{%0,%1,%2,%3}, {%4,%5,%6,%7}, {%8,%9}, {%0,%1,%2,%3};" \
        : "+f"((d)[0]),"+f"((d)[1]),"+f"((d)[2]),"+f"((d)[3]) \
        : "r"((a)[0]),"r"((a)[1]),"r"((a)[2]),"r"((a)[3]), "r"(b0_),"r"(b1_))

// ---------------- scratch (device globals; no allocs allowed) ----------------
__device__ float4 g_wq[Nq];
__device__ int4   g_iq[Nq];
__device__ int    g_cnt[2*NB];
__device__ int    g_off[NB+1];
__device__ int    g_woff[NB];
__device__ int    g_qwoff[NB];
__device__ float4 g_pts[Mp];
__device__ int    g_pidx[Mp];
__device__ int    g_qids[Nq];
__device__ float  g_x0[Nq*C];
__device__ float  g_ya[Nq*C];
__device__ float  g_yb[Nq*C];
__device__ __nv_bfloat16 g_whi[3*C*C];
__device__ __nv_bfloat16 g_wlo[3*C*C];
__device__ float  g_sum[C];
__device__ float  g_sq[C];
__device__ unsigned g_ctr;
__device__ float  g_ab[2*C];

extern __shared__ unsigned char s_raw[];

// ---------------- W -> bf16 hi/lo (once) ----------------
__global__ void __launch_bounds__(256,1) prep_w_kernel(const float* __restrict__ w0,
                                                       const float* __restrict__ w1,
                                                       const float* __restrict__ w2,
                                                       __nv_bfloat16* __restrict__ whi,
                                                       __nv_bfloat16* __restrict__ wlo)
{
    const int b = blockIdx.x;
    const float* w = (b < 64) ? w0 : ((b < 128) ? w1 : w2);
    const int local = (b & 63)*256 + threadIdx.x;
    const int gi = (b >> 6)*16384 + local;
    const float v = w[local];
    const __nv_bfloat16 hi = __float2bfloat16(v);
    whi[gi] = hi;
    wlo[gi] = __float2bfloat16(v - __bfloat162float(hi));
}

// ---------------- norm-bin build ----------------
__device__ __forceinline__ int norm_bin(float x, float y, float z){
    const float np = sqrtf(x*x + y*y + z*z);
    int k = (int)(np * BINV);
    return min(NB-1, max(0, k));
}

__global__ void __launch_bounds__(256,1) build_count_kernel(const float* __restrict__ pos2,
                                                            const float* __restrict__ pos1,
                                                            int* __restrict__ cnt)
{
    const int b = blockIdx.x, t = threadIdx.x;
    if (b < 32){
        const int i = b*256 + t;
        atomicAdd(&cnt[norm_bin(pos2[3*i], pos2[3*i+1], pos2[3*i+2])], 1);
    } else {
        const int i = (b-32)*256 + t;
        atomicAdd(&cnt[NB + norm_bin(pos1[3*i], pos1[3*i+1], pos1[3*i+2])], 1);
    }
}

__global__ void __launch_bounds__(NB,1) scan256_kernel(const int* __restrict__ cnt,
                                                       int* __restrict__ off,
                                                       int* __restrict__ woff,
                                                       int* __restrict__ qwoff)
{
    __shared__ int ws[8];
    const int t = threadIdx.x;
    const int v = cnt[blockIdx.x*NB + t];
    int inc = v;
    #pragma unroll
    for (int d = 1; d < 32; d <<= 1){
        int u = __shfl_up_sync(0xffffffffu, inc, d);
        if ((t & 31) >= d) inc += u;
    }
    if ((t & 31) == 31) ws[t >> 5] = inc;
    __syncthreads();
    if (t < 8){
        int x = ws[t];
        #pragma unroll
        for (int d = 1; d < 8; d <<= 1){
            int u = __shfl_up_sync(0x000000ffu, x, d);
            if (t >= d) x += u;
        }
        ws[t] = x;
    }
    __syncthreads();
    const int excl = inc - v + ((t >= 32) ? ws[(t >> 5) - 1] : 0);
    if (blockIdx.x == 0){
        off[t] = excl;
        woff[t] = excl;
        if (t == NB-1) off[NB] = excl + v;
    } else {
        qwoff[t] = excl;
    }
}

__global__ void __launch_bounds__(256,1) build_scatter_kernel(const float* __restrict__ pos2,
                                                              const float* __restrict__ pos1,
                                                              int* __restrict__ woff,
                                                              int* __restrict__ qwoff,
                                                              float4* __restrict__ pts,
                                                              int* __restrict__ pidx,
                                                              int* __restrict__ qids)
{
    const int b = blockIdx.x, t = threadIdx.x;
    if (b < 32){
        const int i = b*256 + t;
        const float x = pos2[3*i], y = pos2[3*i+1], z = pos2[3*i+2];
        const int slot = atomicAdd(&woff[norm_bin(x,y,z)], 1);
        pts[slot] = make_float4(-2.f*x, -2.f*y, -2.f*z, x*x + y*y + z*z);
        pidx[slot] = i;
    } else {
        const int i = (b-32)*256 + t;
        const int slot = atomicAdd(&qwoff[norm_bin(pos1[3*i], pos1[3*i+1], pos1[3*i+2])], 1);
        qids[slot] = i;
    }
}

// ---------------- norm-sorted kNN: block of 128 norm-adjacent queries ----------------
__global__ void __launch_bounds__(128,4) knn_sorted_kernel(const float* __restrict__ pos1,
                                                           const float4* __restrict__ pts,
                                                           const int* __restrict__ pidx,
                                                           const int* __restrict__ off,
                                                           const int* __restrict__ qids,
                                                           float4* __restrict__ wq,
                                                           int4* __restrict__ iq)
{
    __shared__ ulonglong2 sA[CAPK];   // (.x = x-pair, .y = y-pair) of (-2x)
    __shared__ ulonglong2 sB[CAPK];   // (.x = z-pair, .y = n2-pair)
    __shared__ int2       sI[CAPK];
    __shared__ int s_bmin, s_bmax;

    const int t = threadIdx.x;
    const int n = qids[blockIdx.x*128 + t];
    const float qx = pos1[3*n], qy = pos1[3*n+1], qz = pos1[3*n+2];
    const float n1 = qx*qx + qy*qy + qz*qz;
    const float nq = sqrtf(n1);
    const ull pxx = pk2(qx,qx), pyy = pk2(qy,qy), pzz = pk2(qz,qz);
    const int mybin = min(NB-1, max(0, (int)(nq * BINV)));

    if (t == 0){ s_bmin = NB; s_bmax = -1; }
    __syncthreads();
    atomicMin(&s_bmin, mybin);
    atomicMax(&s_bmax, mybin);
    __syncthreads();
    const int bmin = s_bmin, bmax = s_bmax;

    float t0 = FBIG, t1 = FBIG, t2v = FBIG;
    int   i0 = 0x7fffffff, i1 = 0x7fffffff, i2 = 0x7fffffff;
    bool done = false;
    int lo = bmin, hi = bmax;
    bool first = true;

    while (true){
        int ba, bb;
        if (first){
            ba = bmin; bb = bmax; first = false;
        } else {
            if (__syncthreads_and(done)) break;
            const bool canLo = (lo > 0), canHi = (hi < NB-1);
            if (!canLo && !canHi) break;
            const bool exLo = canLo && (!canHi || (bmin - (lo-1)) <= ((hi+1) - bmax));
            if (exLo){ lo--; ba = lo; bb = lo; }
            else     { hi++; ba = hi; bb = hi; }
        }

        const int cbeg = off[ba], cend = off[bb+1];
        for (int base = cbeg; base < cend; base += 2*CAPK){
            const int cnt  = min(cend - base, 2*CAPK);
            const int npair = (cnt + 1) >> 1;
            __syncthreads();
            for (int s = t; s < npair; s += 128){
                const float4 p0 = pts[base + 2*s];
                const bool hv = (2*s + 1 < cnt);
                const float4 p1 = hv ? pts[base + 2*s + 1] : make_float4(0.f,0.f,0.f,FBIG);
                const int j0 = pidx[base + 2*s];
                const int j1 = hv ? pidx[base + 2*s + 1] : 0x7fffffff;
                ulonglong2 A, B;
                A.x = pk2(p0.x, p1.x);
                A.y = pk2(p0.y, p1.y);
                B.x = pk2(p0.z, p1.z);
                B.y = pk2(p0.w, p1.w);
                sA[s] = A; sB[s] = B;
                sI[s] = make_int2(j0, j1);
            }
            __syncthreads();
            if (!done){
                #pragma unroll 4
                for (int p = 0; p < npair; p++){
                    const ulonglong2 A = sA[p];
                    const ulonglong2 B = sB[p];
                    ull tt = fma2(pzz, B.x, B.y);
                    tt = fma2(pyy, A.y, tt);
                    tt = fma2(pxx, A.x, tt);
                    const float tl = lo2(tt), th = hi2(tt);
                    if (fminf(tl, th) <= t2v){
                        const int2 id = sI[p];
                        ins3i(tl, id.x, t0, t1, t2v, i0, i1, i2);
                        ins3i(th, id.y, t0, t1, t2v, i0, i1, i2);
                    }
                }
            }
        }

        if (!done){
            const float Rlo = (lo > 0)    ? (nq - (float)lo*BW)      : FBIG;
            const float Rhi = (hi < NB-1) ? ((float)(hi+1)*BW - nq)  : FBIG;
            const float R = fminf(Rlo, Rhi) - MARG;
            const float d3 = fmaxf(t2v + n1, 0.f);
            done = (R > 0.f) && (d3 <= R*R);
        }
    }

    const float a0 = fmaxf(t0 + n1, 0.f) + 1e-8f;
    const float a1 = fmaxf(t1 + n1, 0.f) + 1e-8f;
    const float a2 = fmaxf(t2v + n1, 0.f) + 1e-8f;
    const float w0 = 1.f/a0, w1 = 1.f/a1, w2 = 1.f/a2;
    const float inv = 1.f/(w0 + w1 + w2);
    wq[n] = make_float4(w0*inv, w1*inv, w2*inv, 0.f);
    iq[n] = make_int4(i0, i1, i2, 0);
}

// ---------------- interpolation: warp per point ----------------
__global__ void __launch_bounds__(256,1) interp_kernel(const float* __restrict__ feat2,
                                                       const float4* __restrict__ wq,
                                                       const int4*  __restrict__ iq,
                                                       float* __restrict__ x0)
{
    const int gw   = (blockIdx.x*256 + threadIdx.x) >> 5;
    const int lane = threadIdx.x & 31;
    const int4   id = iq[gw];
    const float4 w  = wq[gw];
    const float4* f4 = (const float4*)feat2;
    const float4 a = f4[id.x*32 + lane];
    const float4 b = f4[id.y*32 + lane];
    const float4 c = f4[id.z*32 + lane];
    float4 o;
    o.x = a.x*w.x + b.x*w.y + c.x*w.z;
    o.y = a.y*w.x + b.y*w.y + c.y*w.z;
    o.z = a.z*w.x + b.z*w.y + c.z*w.z;
    o.w = a.w*w.x + b.w*w.y + c.w*w.z;
    ((float4*)x0)[gw*32 + lane] = o;
}

// ---------------- mma.sync split-bf16 GEMM + fused BN epilogue (R13-proven) ----------------
#define RSTR 136
#define TILE_B (128*RSTR*2)
#define O_AHI 0
#define O_ALO (TILE_B)
#define O_BHI (2*TILE_B)
#define O_BLO (3*TILE_B)
#define O_CTL (4*TILE_B)
#define GEMM_SMEM (O_CTL + 1024)

__device__ __forceinline__ unsigned pkbf(__nv_bfloat16 a, __nv_bfloat16 b){
    __nv_bfloat162 h; h.x = a; h.y = b;
    return *(unsigned*)&h;
}

__global__ void __launch_bounds__(256,1)
gemm_tc_kernel(const float* __restrict__ x,
               const __nv_bfloat16* __restrict__ whi,
               const __nv_bfloat16* __restrict__ wlo,
               const float* __restrict__ bias,
               const float* __restrict__ abin,
               const float* __restrict__ g,
               const float* __restrict__ be,
               float* __restrict__ y,
               float* __restrict__ gs,
               float* __restrict__ gq,
               unsigned* __restrict__ ctr,
               float* __restrict__ about)
{
    const unsigned sb = smem_to_u32(s_raw);
    const int t    = threadIdx.x;
    const int wid  = t >> 5, lane = t & 31;
    const int wm   = wid & 3;
    const int wn   = wid >> 2;
    const int blk  = blockIdx.x;
    float* ssum = (float*)(s_raw + O_CTL);
    float* ssq  = (float*)(s_raw + O_CTL + 512);

    if (t < 128){ ssum[t] = 0.f; ssq[t] = 0.f; }

    {
        const bool aff = (abin != 0);
        const float4* x4 = (const float4*)x + (size_t)blk*(128*32);
        #pragma unroll
        for (int i = 0; i < 16; i++){
            const int f = t + i*256;
            const int row = f >> 5, c4 = f & 31;
            float4 v = x4[f];
            if (aff){
                const float4 sc = ((const float4*)abin)[c4];
                const float4 sf = ((const float4*)abin)[32 + c4];
                v.x = fmaxf(fmaf(v.x, sc.x, sf.x), 0.f);
                v.y = fmaxf(fmaf(v.y, sc.y, sf.y), 0.f);
                v.z = fmaxf(fmaf(v.z, sc.z, sf.z), 0.f);
                v.w = fmaxf(fmaf(v.w, sc.w, sf.w), 0.f);
            }
            const __nv_bfloat16 h0 = __float2bfloat16(v.x), h1 = __float2bfloat16(v.y);
            const __nv_bfloat16 h2 = __float2bfloat16(v.z), h3 = __float2bfloat16(v.w);
            const __nv_bfloat16 l0 = __float2bfloat16(v.x - __bfloat162float(h0));
            const __nv_bfloat16 l1 = __float2bfloat16(v.y - __bfloat162float(h1));
            const __nv_bfloat16 l2 = __float2bfloat16(v.z - __bfloat162float(h2));
            const __nv_bfloat16 l3 = __float2bfloat16(v.w - __bfloat162float(h3));
            const unsigned off = (unsigned)(row*(RSTR*2) + c4*8);
            *(uint2*)(s_raw + O_AHI + off) = make_uint2(pkbf(h0,h1), pkbf(h2,h3));
            *(uint2*)(s_raw + O_ALO + off) = make_uint2(pkbf(l0,l1), pkbf(l2,l3));
        }
    }
    {
        #pragma unroll
        for (int i = 0; i < 16; i++){
            const int u = t + i*256;
            const int row = u >> 5, c4 = u & 31;
            const unsigned off = (unsigned)(row*(RSTR*2) + c4*8);
            *(uint2*)(s_raw + O_BHI + off) = *(const uint2*)(whi + row*128 + c4*4);
            *(uint2*)(s_raw + O_BLO + off) = *(const uint2*)(wlo + row*128 + c4*4);
        }
    }
    __syncthreads();

    const unsigned aRowOff = (unsigned)((wm*32 + (lane & 15))*(RSTR*2) + (lane >> 4)*16);
    const unsigned bRowOff = (unsigned)((wn*64 + (lane & 7) + ((lane >> 4) << 3))*(RSTR*2)
                                        + ((lane & 8) ? 16 : 0));

    float acc[2][8][4];
    #pragma unroll
    for (int mi = 0; mi < 2; mi++)
        #pragma unroll
        for (int ni = 0; ni < 8; ni++)
            #pragma unroll
            for (int q = 0; q < 4; q++) acc[mi][ni][q] = 0.f;

    #pragma unroll
    for (int ph = 0; ph < 3; ph++){
        const unsigned abuf = sb + ((ph == 2) ? O_ALO : O_AHI);
        const unsigned bbuf = sb + ((ph == 1) ? O_BLO : O_BHI);
        #pragma unroll
        for (int k0 = 0; k0 < 8; k0++){
            unsigned a0[4], a1[4];
            LDSM_X4(a0, abuf + aRowOff + k0*32);
            LDSM_X4(a1, abuf + aRowOff + 16*(RSTR*2) + k0*32);
            #pragma unroll
            for (int n2 = 0; n2 < 4; n2++){
                unsigned bf[4];
                LDSM_X4(bf, bbuf + bRowOff + n2*16*(RSTR*2) + k0*32);
                MMA16816(acc[0][n2*2],   a0, bf[0], bf[1]);
                MMA16816(acc[0][n2*2+1], a0, bf[2], bf[3]);
                MMA16816(acc[1][n2*2],   a1, bf[0], bf[1]);
                MMA16816(acc[1][n2*2+1], a1, bf[2], bf[3]);
            }
        }
    }

    const int qrow = lane >> 2;
    const int qcol = (lane & 3)*2;
    #pragma unroll
    for (int ni = 0; ni < 8; ni++){
        const int col = wn*64 + ni*8 + qcol;
        const float b0 = __ldg(&bias[col]);
        const float b1 = __ldg(&bias[col+1]);
        float s0 = 0.f, s1 = 0.f, q0 = 0.f, q1 = 0.f;
        #pragma unroll
        for (int mi = 0; mi < 2; mi++){
            const int row = blk*128 + wm*32 + mi*16 + qrow;
            const float v0 = acc[mi][ni][0] + b0;
            const float v1 = acc[mi][ni][1] + b1;
            const float v2 = acc[mi][ni][2] + b0;
            const float v3 = acc[mi][ni][3] + b1;
            *(float2*)(y + (size_t)row*128 + col)       = make_float2(v0, v1);
            *(float2*)(y + (size_t)(row + 8)*128 + col) = make_float2(v2, v3);
            s0 += v0 + v2; s1 += v1 + v3;
            q0 += v0*v0 + v2*v2; q1 += v1*v1 + v3*v3;
        }
        #pragma unroll
        for (int d = 4; d < 32; d <<= 1){
            s0 += __shfl_xor_sync(0xffffffffu, s0, d);
            s1 += __shfl_xor_sync(0xffffffffu, s1, d);
            q0 += __shfl_xor_sync(0xffffffffu, q0, d);
            q1 += __shfl_xor_sync(0xffffffffu, q1, d);
        }
        if (lane < 4){
            atomicAdd(&ssum[col], s0);
            atomicAdd(&ssum[col+1], s1);
            atomicAdd(&ssq[col], q0);
            atomicAdd(&ssq[col+1], q1);
        }
    }
    __syncthreads();
    if (t < 128){
        atomicAdd(&gs[t], ssum[t]);
        atomicAdd(&gq[t], ssq[t]);
    }
    __threadfence();
    __syncthreads();
    __shared__ unsigned s_last;
    if (t == 0){
        const unsigned v = atomicInc(ctr, 255);
        s_last = (v == 255) ? 1u : 0u;
    }
    __syncthreads();
    if (s_last && t < 128){
        const float ss = atomicAdd(&gs[t], 0.f);
        const float qq = atomicAdd(&gq[t], 0.f);
        const float m  = ss * (1.f/32768.f);
        const float vv = qq * (1.f/32768.f) - m*m;
        const float sc = g[t] * rsqrtf(vv + 1e-5f);
        about[t]       = sc;
        about[128 + t] = be[t] - m*sc;
        gs[t] = 0.f;
        gq[t] = 0.f;
    }
}

// ---------------- final BN+ReLU to output ----------------
__global__ void __launch_bounds__(256,1) final_kernel(const float4* __restrict__ y,
                                                      const float* __restrict__ ab,
                                                      float4* __restrict__ out)
{
    const int i = blockIdx.x*256 + threadIdx.x;
    const int c = i & 31;
    const float4 sc = ((const float4*)ab)[c];
    const float4 sf = ((const float4*)ab)[32 + c];
    const float4 v = y[i];
    float4 o;
    o.x = fmaxf(fmaf(v.x, sc.x, sf.x), 0.f);
    o.y = fmaxf(fmaf(v.y, sc.y, sf.y), 0.f);
    o.z = fmaxf(fmaf(v.z, sc.z, sf.z), 0.f);
    o.w = fmaxf(fmaf(v.w, sc.w, sf.w), 0.f);
    out[i] = o;
}

// ---------------- launch ----------------
extern "C" void kernel_launch(void* const* d_in, const int* in_sizes, int n_in,
                              void* d_out, int out_size)
{
    const float* pos1  = (const float*)d_in[0];
    const float* pos2  = (const float*)d_in[1];
    const float* feat2 = (const float*)d_in[2];
    const float* Wm[3]  = {(const float*)d_in[3],  (const float*)d_in[7],  (const float*)d_in[11]};
    const float* bm[3]  = {(const float*)d_in[4],  (const float*)d_in[8],  (const float*)d_in[12]};
    const float* gm[3]  = {(const float*)d_in[5],  (const float*)d_in[9],  (const float*)d_in[13]};
    const float* bem[3] = {(const float*)d_in[6],  (const float*)d_in[10], (const float*)d_in[14]};

    float4 *wq, *pts; int4 *iq; float *x0, *ya, *yb, *gs, *gq, *ab;
    int *cnt, *off, *woff, *qwoff, *pidx, *qids;
    __nv_bfloat16 *whi, *wlo;
    unsigned* ctr;
    cudaGetSymbolAddress((void**)&wq, g_wq);
    cudaGetSymbolAddress((void**)&iq, g_iq);
    cudaGetSymbolAddress((void**)&cnt, g_cnt);
    cudaGetSymbolAddress((void**)&off, g_off);
    cudaGetSymbolAddress((void**)&woff, g_woff);
    cudaGetSymbolAddress((void**)&qwoff, g_qwoff);
    cudaGetSymbolAddress((void**)&pts, g_pts);
    cudaGetSymbolAddress((void**)&pidx, g_pidx);
    cudaGetSymbolAddress((void**)&qids, g_qids);
    cudaGetSymbolAddress((void**)&x0, g_x0);
    cudaGetSymbolAddress((void**)&ya, g_ya);
    cudaGetSymbolAddress((void**)&yb, g_yb);
    cudaGetSymbolAddress((void**)&whi, g_whi);
    cudaGetSymbolAddress((void**)&wlo, g_wlo);
    cudaGetSymbolAddress((void**)&gs, g_sum);
    cudaGetSymbolAddress((void**)&gq, g_sq);
    cudaGetSymbolAddress((void**)&ctr, g_ctr);
    cudaGetSymbolAddress((void**)&ab, g_ab);

    cudaFuncSetAttribute(gemm_tc_kernel, cudaFuncAttributeMaxDynamicSharedMemorySize, GEMM_SMEM);

    prep_w_kernel<<<192,256>>>(Wm[0], Wm[1], Wm[2], whi, wlo);

    cudaMemsetAsync(cnt, 0, 2*NB*sizeof(int), 0);
    build_count_kernel<<<160,256>>>(pos2, pos1, cnt);
    scan256_kernel<<<2,NB>>>(cnt, off, woff, qwoff);
    build_scatter_kernel<<<160,256>>>(pos2, pos1, woff, qwoff, pts, pidx, qids);
    knn_sorted_kernel<<<Nq/128,128>>>(pos1, pts, pidx, off, qids, wq, iq);

    interp_kernel<<<4096,256>>>(feat2, wq, iq, x0);

    gemm_tc_kernel<<<256,256,GEMM_SMEM>>>(x0, whi,         wlo,         bm[0], 0,  gm[0], bem[0], ya, gs, gq, ctr, ab);
    gemm_tc_kernel<<<256,256,GEMM_SMEM>>>(ya, whi + 16384, wlo + 16384, bm[1], ab, gm[1], bem[1], yb, gs, gq, ctr, ab);
    gemm_tc_kernel<<<256,256,GEMM_SMEM>>>(yb, whi + 32768, wlo + 32768, bm[2], ab, gm[2], bem[2], x0, gs, gq, ctr, ab);
    final_kernel<<<4096,256>>>((const float4*)x0, ab, (float4*)d_out);
}

// round 15
// speedup vs baseline: 1.1277x; 1.1277x over previous
#include <cuda_runtime.h>
#include <cuda_bf16.h>

#define Nq 32768
#define Mp 8192
#define C  128

// ---- knn config (R6/R13-proven) ----
#define KTPB 128
#define KQB  128
#define NCH  4
#define KHALF (Mp/NCH)
#define SUB  512
#define NSUB (KHALF/2/SUB)

typedef unsigned long long ull;

union F2U { float2 f; ull u; };
__device__ __forceinline__ ull pk2(float a, float b){ F2U t; t.f.x=a; t.f.y=b; return t.u; }
__device__ __forceinline__ float lo2(ull v){ F2U t; t.u=v; return t.f.x; }
__device__ __forceinline__ float hi2(ull v){ F2U t; t.u=v; return t.f.y; }
__device__ __forceinline__ ull fma2(ull a, ull b, ull c){
    ull d; asm("fma.rn.f32x2 %0, %1, %2, %3;" : "=l"(d) : "l"(a), "l"(b), "l"(c)); return d;
}

// branchless stable top-3 insert (strict < => ties keep earlier-seen/lower index)
__device__ __forceinline__ void ins3(float t, int idx,
                                     float& d0, float& d1, float& d2,
                                     int& i0, int& i1, int& i2)
{
    const bool c0 = t < d0, c1 = t < d1, c2 = t < d2;
    d2 = c1 ? d1 : (c2 ? t : d2);
    i2 = c1 ? i1 : (c2 ? idx : i2);
    d1 = c0 ? d0 : (c1 ? t : d1);
    i1 = c0 ? i0 : (c1 ? idx : i1);
    d0 = c0 ? t : d0;
    i0 = c0 ? idx : i0;
}

__device__ __forceinline__ unsigned smem_to_u32(const void* p){
    unsigned a;
    asm("{ .reg .u64 tmp; cvta.to.shared.u64 tmp, %1; cvt.u32.u64 %0, tmp; }" : "=r"(a) : "l"(p));
    return a;
}

#define LDSM_X4(r, addr) \
    asm volatile("ldmatrix.sync.aligned.m8n8.x4.shared.b16 {%0,%1,%2,%3}, [%4];" \
        : "=r"((r)[0]),"=r"((r)[1]),"=r"((r)[2]),"=r"((r)[3]) : "r"(addr))

#define MMA16816(d, a, b0_, b1_) \
    asm volatile("mma.sync.aligned.m16n8k16.row.col.f32.bf16.bf16.f32 " \
        "{%0,%1,%2,%3}, {%4,%5,%6,%7}, {%8,%9}, {%0,%1,%2,%3};" \
        : "+f"((d)[0]),"+f"((d)[1]),"+f"((d)[2]),"+f"((d)[3]) \
        : "r"((a)[0]),"r"((a)[1]),"r"((a)[2]),"r"((a)[3]), "r"(b0_),"r"(b1_))

// ---------------- scratch (device globals; no allocs allowed) ----------------
__device__ float4 g_wq[Nq];
__device__ int4   g_iq[Nq];
__device__ float4 g_pd[NCH*Nq];
__device__ int4   g_pi[NCH*Nq];
__device__ float  g_x0[Nq*C];
__device__ float  g_ya[Nq*C];
__device__ float  g_yb[Nq*C];
__device__ __nv_bfloat16 g_whi[3*C*C];
__device__ __nv_bfloat16 g_wlo[3*C*C];
__device__ float  g_sum[C];
__device__ float  g_sq[C];
__device__ unsigned g_ctr;
__device__ float  g_ab[2*C];

extern __shared__ unsigned char s_raw[];

// ---------------- W -> bf16 hi/lo (once) ----------------
__global__ void __launch_bounds__(256,1) prep_w_kernel(const float* __restrict__ w0,
                                                       const float* __restrict__ w1,
                                                       const float* __restrict__ w2,
                                                       __nv_bfloat16* __restrict__ whi,
                                                       __nv_bfloat16* __restrict__ wlo)
{
    const int b = blockIdx.x;                   // 192 blocks
    const float* w = (b < 64) ? w0 : ((b < 128) ? w1 : w2);
    const int local = (b & 63)*256 + threadIdx.x;
    const int gi = (b >> 6)*16384 + local;
    const float v = w[local];
    const __nv_bfloat16 hi = __float2bfloat16(v);
    whi[gi] = hi;
    wlo[gi] = __float2bfloat16(v - __bfloat162float(hi));
}

// -------- kNN partial (R6-proven) --------
__global__ void __launch_bounds__(KTPB,8) knn_part_kernel(const float* __restrict__ pos1,
                                                          const float* __restrict__ pos2,
                                                          float4* __restrict__ pd,
                                                          int4*  __restrict__ pi)
{
    __shared__ ulonglong2 sA[SUB];
    __shared__ ulonglong2 sB[SUB];
    const int t     = threadIdx.x;
    const int chunk = blockIdx.x & (NCH-1);
    const int n     = (blockIdx.x >> 2) * KQB + t;

    const float px = pos1[3*n], py = pos1[3*n+1], pz = pos1[3*n+2];
    const ull pxx = pk2(px,px), pyy = pk2(py,py), pzz = pk2(pz,pz);

    float d0=3.4e38f, d1=3.4e38f, d2=3.4e38f;
    int   i0=0, i1=0, i2=0;

    const int pb0 = chunk * (KHALF/2);

    for (int sc = 0; sc < NSUB; sc++){
        const int pb = pb0 + sc*SUB;
        __syncthreads();
        #pragma unroll
        for (int i = 0; i < SUB/KTPB; i++){
            const int p = t + i*KTPB;
            const float2* q2 = (const float2*)(pos2 + 6*(pb + p));
            const float2 a = q2[0], b = q2[1], c = q2[2];
            const float x0=a.x, y0=a.y, z0=b.x, x1=b.y, y1=c.x, z1=c.y;
            const float n0 = x0*x0 + y0*y0 + z0*z0;
            const float n1 = x1*x1 + y1*y1 + z1*z1;
            ulonglong2 A, B;
            A.x = pk2(-2.f*x0, -2.f*x1);
            A.y = pk2(-2.f*y0, -2.f*y1);
            B.x = pk2(-2.f*z0, -2.f*z1);
            B.y = pk2(n0, n1);
            sA[p] = A; sB[p] = B;
        }
        __syncthreads();

        #pragma unroll 4
        for (int p = 0; p < SUB; p++){
            const ulonglong2 A = sA[p];
            const ulonglong2 B = sB[p];
            ull tt = fma2(pzz, B.x, B.y);
            tt = fma2(pyy, A.y, tt);
            tt = fma2(pxx, A.x, tt);
            const float tl = lo2(tt), th = hi2(tt);
            if (fminf(tl, th) < d2){
                const int g = 2*(pb + p);
                ins3(tl, g,   d0, d1, d2, i0, i1, i2);
                ins3(th, g+1, d0, d1, d2, i0, i1, i2);
            }
        }
    }

    pd[chunk*Nq + n] = make_float4(d0, d1, d2, 0.f);
    pi[chunk*Nq + n] = make_int4(i0, i1, i2, 0);
}

// ---------------- merge partials -> weights/indices (R6) ----------------
__global__ void __launch_bounds__(256,1) knn_merge_kernel(const float* __restrict__ pos1,
                                                          const float4* __restrict__ pd,
                                                          const int4*  __restrict__ pi,
                                                          float4* __restrict__ wq,
                                                          int4*  __restrict__ iq)
{
    const int n = blockIdx.x*256 + threadIdx.x;
    float4 v = pd[n];
    int4  id = pi[n];
    float d0=v.x, d1=v.y, d2=v.z;
    int   i0=id.x, i1=id.y, i2=id.z;

    #pragma unroll
    for (int c = 1; c < NCH; c++){
        const float4 e = pd[c*Nq + n];
        const int4   j = pi[c*Nq + n];
        ins3(e.x, j.x, d0, d1, d2, i0, i1, i2);
        ins3(e.y, j.y, d0, d1, d2, i0, i1, i2);
        ins3(e.z, j.z, d0, d1, d2, i0, i1, i2);
    }

    const float px = pos1[3*n], py = pos1[3*n+1], pz = pos1[3*n+2];
    const float n1 = px*px + py*py + pz*pz;
    const float a0 = fmaxf(d0 + n1, 0.f) + 1e-8f;
    const float a1 = fmaxf(d1 + n1, 0.f) + 1e-8f;
    const float a2 = fmaxf(d2 + n1, 0.f) + 1e-8f;
    const float w0 = 1.f/a0, w1 = 1.f/a1, w2 = 1.f/a2;
    const float inv = 1.f/(w0 + w1 + w2);
    wq[n] = make_float4(w0*inv, w1*inv, w2*inv, 0.f);
    iq[n] = make_int4(i0, i1, i2, 0);
}

// ---------------- interpolation: warp per point (R6) ----------------
__global__ void __launch_bounds__(256,1) interp_kernel(const float* __restrict__ feat2,
                                                       const float4* __restrict__ wq,
                                                       const int4*  __restrict__ iq,
                                                       float* __restrict__ x0)
{
    const int gw   = (blockIdx.x*256 + threadIdx.x) >> 5;
    const int lane = threadIdx.x & 31;
    const int4   id = iq[gw];
    const float4 w  = wq[gw];
    const float4* f4 = (const float4*)feat2;
    const float4 a = f4[id.x*32 + lane];
    const float4 b = f4[id.y*32 + lane];
    const float4 c = f4[id.z*32 + lane];
    float4 o;
    o.x = a.x*w.x + b.x*w.y + c.x*w.z;
    o.y = a.y*w.x + b.y*w.y + c.y*w.z;
    o.z = a.z*w.x + b.z*w.y + c.z*w.z;
    o.w = a.w*w.x + b.w*w.y + c.w*w.z;
    ((float4*)x0)[gw*32 + lane] = o;
}

// ---------------- mma.sync split-bf16 GEMM + fused BN epilogue ----------------
// 3-buffer variant for 2 CTAs/SM: Ahi, Alo, B (Bhi then restaged to Blo).
#define RSTR 136
#define TILE_B (128*RSTR*2)           // 34816 bytes per tile
#define O_AHI 0
#define O_ALO (TILE_B)
#define O_B   (2*TILE_B)
#define O_CTL (3*TILE_B)              // 104448
#define GEMM_SMEM (O_CTL + 1024)

__device__ __forceinline__ unsigned pkbf(__nv_bfloat16 a, __nv_bfloat16 b){
    __nv_bfloat162 h; h.x = a; h.y = b;
    return *(unsigned*)&h;
}

__global__ void __launch_bounds__(256,2)
gemm_tc_kernel(const float* __restrict__ x,
               const __nv_bfloat16* __restrict__ whi,
               const __nv_bfloat16* __restrict__ wlo,
               const float* __restrict__ bias,
               const float* __restrict__ abin,   // prev scale|shift or null
               const float* __restrict__ g,
               const float* __restrict__ be,
               float* __restrict__ y,
               float* __restrict__ gs,
               float* __restrict__ gq,
               unsigned* __restrict__ ctr,
               float* __restrict__ about)
{
    const unsigned sb = smem_to_u32(s_raw);
    const int t    = threadIdx.x;
    const int wid  = t >> 5, lane = t & 31;
    const int wm   = wid & 3;            // m block: wm*32
    const int wn   = wid >> 2;           // n block: wn*64
    const int blk  = blockIdx.x;
    float* ssum = (float*)(s_raw + O_CTL);
    float* ssq  = (float*)(s_raw + O_CTL + 512);

    if (t < 128){ ssum[t] = 0.f; ssq[t] = 0.f; }

    { // stage X tile -> bf16 hi/lo (fused affine+relu), padded row-major
        const bool aff = (abin != 0);
        const float4* x4 = (const float4*)x + (size_t)blk*(128*32);
        #pragma unroll
        for (int i = 0; i < 16; i++){
            const int f = t + i*256;          // 0..4095 float4s
            const int row = f >> 5, c4 = f & 31;
            float4 v = x4[f];
            if (aff){
                const float4 sc = ((const float4*)abin)[c4];
                const float4 sf = ((const float4*)abin)[32 + c4];
                v.x = fmaxf(fmaf(v.x, sc.x, sf.x), 0.f);
                v.y = fmaxf(fmaf(v.y, sc.y, sf.y), 0.f);
                v.z = fmaxf(fmaf(v.z, sc.z, sf.z), 0.f);
                v.w = fmaxf(fmaf(v.w, sc.w, sf.w), 0.f);
            }
            const __nv_bfloat16 h0 = __float2bfloat16(v.x), h1 = __float2bfloat16(v.y);
            const __nv_bfloat16 h2 = __float2bfloat16(v.z), h3 = __float2bfloat16(v.w);
            const __nv_bfloat16 l0 = __float2bfloat16(v.x - __bfloat162float(h0));
            const __nv_bfloat16 l1 = __float2bfloat16(v.y - __bfloat162float(h1));
            const __nv_bfloat16 l2 = __float2bfloat16(v.z - __bfloat162float(h2));
            const __nv_bfloat16 l3 = __float2bfloat16(v.w - __bfloat162float(h3));
            const unsigned off = (unsigned)(row*(RSTR*2) + c4*8);
            *(uint2*)(s_raw + O_AHI + off) = make_uint2(pkbf(h0,h1), pkbf(h2,h3));
            *(uint2*)(s_raw + O_ALO + off) = make_uint2(pkbf(l0,l1), pkbf(l2,l3));
        }
    }
    { // stage W hi ([j][k] row-major), padded
        #pragma unroll
        for (int i = 0; i < 16; i++){
            const int u = t + i*256;
            const int row = u >> 5, c4 = u & 31;
            const unsigned off = (unsigned)(row*(RSTR*2) + c4*8);
            *(uint2*)(s_raw + O_B + off) = *(const uint2*)(whi + row*128 + c4*4);
        }
    }
    __syncthreads();

    // per-thread ldmatrix address components
    const unsigned aRowOff = (unsigned)((wm*32 + (lane & 15))*(RSTR*2) + (lane >> 4)*16);
    const unsigned bRowOff = (unsigned)((wn*64 + (lane & 7) + ((lane >> 4) << 3))*(RSTR*2)
                                        + ((lane & 8) ? 16 : 0));

    float acc[2][8][4];
    #pragma unroll
    for (int mi = 0; mi < 2; mi++)
        #pragma unroll
        for (int ni = 0; ni < 8; ni++)
            #pragma unroll
            for (int q = 0; q < 4; q++) acc[mi][ni][q] = 0.f;

    // pass macro: one full K sweep with given A buffer against current B buffer
    #define K_SWEEP(AOFF)                                                        \
        _Pragma("unroll")                                                        \
        for (int k0 = 0; k0 < 8; k0++){                                          \
            unsigned a0[4], a1[4];                                               \
            LDSM_X4(a0, sb + (AOFF) + aRowOff + k0*32);                          \
            LDSM_X4(a1, sb + (AOFF) + aRowOff + 16*(RSTR*2) + k0*32);            \
            _Pragma("unroll")                                                    \
            for (int n2 = 0; n2 < 4; n2++){                                      \
                unsigned bf[4];                                                  \
                LDSM_X4(bf, sb + O_B + bRowOff + n2*16*(RSTR*2) + k0*32);        \
                MMA16816(acc[0][n2*2],   a0, bf[0], bf[1]);                      \
                MMA16816(acc[0][n2*2+1], a0, bf[2], bf[3]);                      \
                MMA16816(acc[1][n2*2],   a1, bf[0], bf[1]);                      \
                MMA16816(acc[1][n2*2+1], a1, bf[2], bf[3]);                      \
            }                                                                    \
        }

    K_SWEEP(O_AHI)      // Ahi x Whi
    K_SWEEP(O_ALO)      // Alo x Whi
    __syncthreads();    // all warps done reading B(=Whi)
    { // restage B <- Wlo
        #pragma unroll
        for (int i = 0; i < 16; i++){
            const int u = t + i*256;
            const int row = u >> 5, c4 = u & 31;
            const unsigned off = (unsigned)(row*(RSTR*2) + c4*8);
            *(uint2*)(s_raw + O_B + off) = *(const uint2*)(wlo + row*128 + c4*4);
        }
    }
    __syncthreads();
    K_SWEEP(O_AHI)      // Ahi x Wlo
    #undef K_SWEEP

    // epilogue: +bias, write y, column stats
    const int qrow = lane >> 2;            // 0..7
    const int qcol = (lane & 3)*2;
    #pragma unroll
    for (int ni = 0; ni < 8; ni++){
        const int col = wn*64 + ni*8 + qcol;
        const float b0 = __ldg(&bias[col]);
        const float b1 = __ldg(&bias[col+1]);
        float s0 = 0.f, s1 = 0.f, q0 = 0.f, q1 = 0.f;
        #pragma unroll
        for (int mi = 0; mi < 2; mi++){
            const int row = blk*128 + wm*32 + mi*16 + qrow;
            const float v0 = acc[mi][ni][0] + b0;
            const float v1 = acc[mi][ni][1] + b1;
            const float v2 = acc[mi][ni][2] + b0;
            const float v3 = acc[mi][ni][3] + b1;
            *(float2*)(y + (size_t)row*128 + col)       = make_float2(v0, v1);
            *(float2*)(y + (size_t)(row + 8)*128 + col) = make_float2(v2, v3);
            s0 += v0 + v2; s1 += v1 + v3;
            q0 += v0*v0 + v2*v2; q1 += v1*v1 + v3*v3;
        }
        #pragma unroll
        for (int d = 4; d < 32; d <<= 1){
            s0 += __shfl_xor_sync(0xffffffffu, s0, d);
            s1 += __shfl_xor_sync(0xffffffffu, s1, d);
            q0 += __shfl_xor_sync(0xffffffffu, q0, d);
            q1 += __shfl_xor_sync(0xffffffffu, q1, d);
        }
        if (lane < 4){
            atomicAdd(&ssum[col], s0);
            atomicAdd(&ssum[col+1], s1);
            atomicAdd(&ssq[col], q0);
            atomicAdd(&ssq[col+1], q1);
        }
    }
    __syncthreads();
    if (t < 128){
        atomicAdd(&gs[t], ssum[t]);
        atomicAdd(&gq[t], ssq[t]);
    }
    __threadfence();
    __syncthreads();
    __shared__ unsigned s_last;
    if (t == 0){
        const unsigned v = atomicInc(ctr, 255);   // grid=256
        s_last = (v == 255) ? 1u : 0u;
    }
    __syncthreads();
    if (s_last && t < 128){
        const float ss = atomicAdd(&gs[t], 0.f);
        const float qq = atomicAdd(&gq[t], 0.f);
        const float m  = ss * (1.f/32768.f);
        const float vv = qq * (1.f/32768.f) - m*m;
        const float sc = g[t] * rsqrtf(vv + 1e-5f);
        about[t]       = sc;
        about[128 + t] = be[t] - m*sc;
        gs[t] = 0.f;
        gq[t] = 0.f;
    }
}

// ---------------- final BN+ReLU to output ----------------
__global__ void __launch_bounds__(256,1) final_kernel(const float4* __restrict__ y,
                                                      const float* __restrict__ ab,
                                                      float4* __restrict__ out)
{
    const int i = blockIdx.x*256 + threadIdx.x;
    const int c = i & 31;
    const float4 sc = ((const float4*)ab)[c];
    const float4 sf = ((const float4*)ab)[32 + c];
    const float4 v = y[i];
    float4 o;
    o.x = fmaxf(fmaf(v.x, sc.x, sf.x), 0.f);
    o.y = fmaxf(fmaf(v.y, sc.y, sf.y), 0.f);
    o.z = fmaxf(fmaf(v.z, sc.z, sf.z), 0.f);
    o.w = fmaxf(fmaf(v.w, sc.w, sf.w), 0.f);
    out[i] = o;
}

// ---------------- launch ----------------
extern "C" void kernel_launch(void* const* d_in, const int* in_sizes, int n_in,
                              void* d_out, int out_size)
{
    const float* pos1  = (const float*)d_in[0];
    const float* pos2  = (const float*)d_in[1];
    const float* feat2 = (const float*)d_in[2];
    const float* Wm[3]  = {(const float*)d_in[3],  (const float*)d_in[7],  (const float*)d_in[11]};
    const float* bm[3]  = {(const float*)d_in[4],  (const float*)d_in[8],  (const float*)d_in[12]};
    const float* gm[3]  = {(const float*)d_in[5],  (const float*)d_in[9],  (const float*)d_in[13]};
    const float* bem[3] = {(const float*)d_in[6],  (const float*)d_in[10], (const float*)d_in[14]};

    float4 *wq, *pdist; int4 *iq, *pidx; float *x0, *ya, *yb, *gs, *gq, *ab;
    __nv_bfloat16 *whi, *wlo;
    unsigned* ctr;
    cudaGetSymbolAddress((void**)&wq, g_wq);
    cudaGetSymbolAddress((void**)&iq, g_iq);
    cudaGetSymbolAddress((void**)&pdist, g_pd);
    cudaGetSymbolAddress((void**)&pidx, g_pi);
    cudaGetSymbolAddress((void**)&x0, g_x0);
    cudaGetSymbolAddress((void**)&ya, g_ya);
    cudaGetSymbolAddress((void**)&yb, g_yb);
    cudaGetSymbolAddress((void**)&whi, g_whi);
    cudaGetSymbolAddress((void**)&wlo, g_wlo);
    cudaGetSymbolAddress((void**)&gs, g_sum);
    cudaGetSymbolAddress((void**)&gq, g_sq);
    cudaGetSymbolAddress((void**)&ctr, g_ctr);
    cudaGetSymbolAddress((void**)&ab, g_ab);

    cudaFuncSetAttribute(gemm_tc_kernel, cudaFuncAttributeMaxDynamicSharedMemorySize, GEMM_SMEM);

    prep_w_kernel<<<192,256>>>(Wm[0], Wm[1], Wm[2], whi, wlo);

    knn_part_kernel<<<(Nq/KQB)*NCH, KTPB>>>(pos1, pos2, pdist, pidx);
    knn_merge_kernel<<<Nq/256, 256>>>(pos1, pdist, pidx, wq, iq);
    interp_kernel<<<4096,256>>>(feat2, wq, iq, x0);

    gemm_tc_kernel<<<256,256,GEMM_SMEM>>>(x0, whi,         wlo,         bm[0], 0,  gm[0], bem[0], ya, gs, gq, ctr, ab);
    gemm_tc_kernel<<<256,256,GEMM_SMEM>>>(ya, whi + 16384, wlo + 16384, bm[1], ab, gm[1], bem[1], yb, gs, gq, ctr, ab);
    gemm_tc_kernel<<<256,256,GEMM_SMEM>>>(yb, whi + 32768, wlo + 32768, bm[2], ab, gm[2], bem[2], x0, gs, gq, ctr, ab);
    final_kernel<<<4096,256>>>((const float4*)x0, ab, (float4*)d_out);
}

// round 16
// speedup vs baseline: 1.2983x; 1.1513x over previous
#include <cuda_runtime.h>
#include <cuda_bf16.h>

#define Nq 32768
#define Mp 8192
#define C  128

// ---- knn config (R6/R13-proven) ----
#define KTPB 128
#define KQB  128
#define NCH  4
#define KHALF (Mp/NCH)
#define SUB  512
#define NSUB (KHALF/2/SUB)

typedef unsigned long long ull;

union F2U { float2 f; ull u; };
__device__ __forceinline__ ull pk2(float a, float b){ F2U t; t.f.x=a; t.f.y=b; return t.u; }
__device__ __forceinline__ float lo2(ull v){ F2U t; t.u=v; return t.f.x; }
__device__ __forceinline__ float hi2(ull v){ F2U t; t.u=v; return t.f.y; }
__device__ __forceinline__ ull fma2(ull a, ull b, ull c){
    ull d; asm("fma.rn.f32x2 %0, %1, %2, %3;" : "=l"(d) : "l"(a), "l"(b), "l"(c)); return d;
}

// branchless stable top-3 insert (strict < => ties keep earlier-seen/lower index)
__device__ __forceinline__ void ins3(float t, int idx,
                                     float& d0, float& d1, float& d2,
                                     int& i0, int& i1, int& i2)
{
    const bool c0 = t < d0, c1 = t < d1, c2 = t < d2;
    d2 = c1 ? d1 : (c2 ? t : d2);
    i2 = c1 ? i1 : (c2 ? idx : i2);
    d1 = c0 ? d0 : (c1 ? t : d1);
    i1 = c0 ? i0 : (c1 ? idx : i1);
    d0 = c0 ? t : d0;
    i0 = c0 ? idx : i0;
}

__device__ __forceinline__ unsigned smem_to_u32(const void* p){
    unsigned a;
    asm("{ .reg .u64 tmp; cvta.to.shared.u64 tmp, %1; cvt.u32.u64 %0, tmp; }" : "=r"(a) : "l"(p));
    return a;
}

#define LDSM_X4(r, addr) \
    asm volatile("ldmatrix.sync.aligned.m8n8.x4.shared.b16 {%0,%1,%2,%3}, [%4];" \
        : "=r"((r)[0]),"=r"((r)[1]),"=r"((r)[2]),"=r"((r)[3]) : "r"(addr))

#define MMA16816(d, a, b0_, b1_) \
    asm volatile("mma.sync.aligned.m16n8k16.row.col.f32.bf16.bf16.f32 " \
        "{%0,%1,%2,%3}, {%4,%5,%6,%7}, {%8,%9}, {%0,%1,%2,%3};" \
        : "+f"((d)[0]),"+f"((d)[1]),"+f"((d)[2]),"+f"((d)[3]) \
        : "r"((a)[0]),"r"((a)[1]),"r"((a)[2]),"r"((a)[3]), "r"(b0_),"r"(b1_))

// ---------------- scratch (device globals; no allocs allowed) ----------------
__device__ float4 g_wq[Nq];
__device__ int4   g_iq[Nq];
__device__ float4 g_pd[NCH*Nq];
__device__ int4   g_pi[NCH*Nq];
__device__ float  g_x0[Nq*C];
__device__ float  g_ya[Nq*C];
__device__ float  g_yb[Nq*C];
__device__ __nv_bfloat16 g_whi[3*C*C];
__device__ __nv_bfloat16 g_wlo[3*C*C];
__device__ float  g_sum[C];
__device__ float  g_sq[C];
__device__ unsigned g_ctr;
__device__ float  g_ab[2*C];

extern __shared__ unsigned char s_raw[];

// ---------------- W -> bf16 hi/lo (once) ----------------
__global__ void __launch_bounds__(256,1) prep_w_kernel(const float* __restrict__ w0,
                                                       const float* __restrict__ w1,
                                                       const float* __restrict__ w2,
                                                       __nv_bfloat16* __restrict__ whi,
                                                       __nv_bfloat16* __restrict__ wlo)
{
    const int b = blockIdx.x;                   // 192 blocks
    const float* w = (b < 64) ? w0 : ((b < 128) ? w1 : w2);
    const int local = (b & 63)*256 + threadIdx.x;
    const int gi = (b >> 6)*16384 + local;
    const float v = w[local];
    const __nv_bfloat16 hi = __float2bfloat16(v);
    whi[gi] = hi;
    wlo[gi] = __float2bfloat16(v - __bfloat162float(hi));
}

// -------- kNN partial (R6-proven; split guards) --------
__global__ void __launch_bounds__(KTPB,8) knn_part_kernel(const float* __restrict__ pos1,
                                                          const float* __restrict__ pos2,
                                                          float4* __restrict__ pd,
                                                          int4*  __restrict__ pi)
{
    __shared__ ulonglong2 sA[SUB];
    __shared__ ulonglong2 sB[SUB];
    const int t     = threadIdx.x;
    const int chunk = blockIdx.x & (NCH-1);
    const int n     = (blockIdx.x >> 2) * KQB + t;

    const float px = pos1[3*n], py = pos1[3*n+1], pz = pos1[3*n+2];
    const ull pxx = pk2(px,px), pyy = pk2(py,py), pzz = pk2(pz,pz);

    float d0=3.4e38f, d1=3.4e38f, d2=3.4e38f;
    int   i0=0, i1=0, i2=0;

    const int pb0 = chunk * (KHALF/2);

    for (int sc = 0; sc < NSUB; sc++){
        const int pb = pb0 + sc*SUB;
        __syncthreads();
        #pragma unroll
        for (int i = 0; i < SUB/KTPB; i++){
            const int p = t + i*KTPB;
            const float2* q2 = (const float2*)(pos2 + 6*(pb + p));
            const float2 a = q2[0], b = q2[1], c = q2[2];
            const float x0=a.x, y0=a.y, z0=b.x, x1=b.y, y1=c.x, z1=c.y;
            const float n0 = x0*x0 + y0*y0 + z0*z0;
            const float n1 = x1*x1 + y1*y1 + z1*z1;
            ulonglong2 A, B;
            A.x = pk2(-2.f*x0, -2.f*x1);
            A.y = pk2(-2.f*y0, -2.f*y1);
            B.x = pk2(-2.f*z0, -2.f*z1);
            B.y = pk2(n0, n1);
            sA[p] = A; sB[p] = B;
        }
        __syncthreads();

        #pragma unroll 4
        for (int p = 0; p < SUB; p++){
            const ulonglong2 A = sA[p];
            const ulonglong2 B = sB[p];
            ull tt = fma2(pzz, B.x, B.y);
            tt = fma2(pyy, A.y, tt);
            tt = fma2(pxx, A.x, tt);
            const float tl = lo2(tt), th = hi2(tt);
            const int g = 2*(pb + p);
            if (tl < d2) ins3(tl, g,   d0, d1, d2, i0, i1, i2);
            if (th < d2) ins3(th, g+1, d0, d1, d2, i0, i1, i2);
        }
    }

    pd[chunk*Nq + n] = make_float4(d0, d1, d2, 0.f);
    pi[chunk*Nq + n] = make_int4(i0, i1, i2, 0);
}

// ---------------- merge partials -> weights/indices (R6) ----------------
__global__ void __launch_bounds__(256,1) knn_merge_kernel(const float* __restrict__ pos1,
                                                          const float4* __restrict__ pd,
                                                          const int4*  __restrict__ pi,
                                                          float4* __restrict__ wq,
                                                          int4*  __restrict__ iq)
{
    const int n = blockIdx.x*256 + threadIdx.x;
    float4 v = pd[n];
    int4  id = pi[n];
    float d0=v.x, d1=v.y, d2=v.z;
    int   i0=id.x, i1=id.y, i2=id.z;

    #pragma unroll
    for (int c = 1; c < NCH; c++){
        const float4 e = pd[c*Nq + n];
        const int4   j = pi[c*Nq + n];
        ins3(e.x, j.x, d0, d1, d2, i0, i1, i2);
        ins3(e.y, j.y, d0, d1, d2, i0, i1, i2);
        ins3(e.z, j.z, d0, d1, d2, i0, i1, i2);
    }

    const float px = pos1[3*n], py = pos1[3*n+1], pz = pos1[3*n+2];
    const float n1 = px*px + py*py + pz*pz;
    const float a0 = fmaxf(d0 + n1, 0.f) + 1e-8f;
    const float a1 = fmaxf(d1 + n1, 0.f) + 1e-8f;
    const float a2 = fmaxf(d2 + n1, 0.f) + 1e-8f;
    const float w0 = 1.f/a0, w1 = 1.f/a1, w2 = 1.f/a2;
    const float inv = 1.f/(w0 + w1 + w2);
    wq[n] = make_float4(w0*inv, w1*inv, w2*inv, 0.f);
    iq[n] = make_int4(i0, i1, i2, 0);
}

// ---------------- mma.sync split-bf16 GEMM + fused BN epilogue (R13-proven) -------------
// Layer 1 additionally fuses the kNN interpolation gather into the X-stage.
#define RSTR 136
#define TILE_B (128*RSTR*2)
#define O_AHI 0
#define O_ALO (TILE_B)
#define O_BHI (2*TILE_B)
#define O_BLO (3*TILE_B)
#define O_CTL (4*TILE_B)
#define GEMM_SMEM (O_CTL + 1024)

__device__ __forceinline__ unsigned pkbf(__nv_bfloat16 a, __nv_bfloat16 b){
    __nv_bfloat162 h; h.x = a; h.y = b;
    return *(unsigned*)&h;
}

__global__ void __launch_bounds__(256,1)
gemm_tc_kernel(const float* __restrict__ x,          // null for layer 1 (gather path)
               const float4* __restrict__ wqp,       // layer-1 gather inputs
               const int4*  __restrict__ iqp,
               const float* __restrict__ feat2,
               const __nv_bfloat16* __restrict__ whi,
               const __nv_bfloat16* __restrict__ wlo,
               const float* __restrict__ bias,
               const float* __restrict__ abin,       // prev scale|shift or null
               const float* __restrict__ g,
               const float* __restrict__ be,
               float* __restrict__ y,
               float* __restrict__ gs,
               float* __restrict__ gq,
               unsigned* __restrict__ ctr,
               float* __restrict__ about)
{
    const unsigned sb = smem_to_u32(s_raw);
    const int t    = threadIdx.x;
    const int wid  = t >> 5, lane = t & 31;
    const int wm   = wid & 3;
    const int wn   = wid >> 2;
    const int blk  = blockIdx.x;
    float* ssum = (float*)(s_raw + O_CTL);
    float* ssq  = (float*)(s_raw + O_CTL + 512);

    if (t < 128){ ssum[t] = 0.f; ssq[t] = 0.f; }

    { // stage X tile -> bf16 hi/lo; layer1: gather interp inline; else affine+relu
        const bool gat = (x == 0);
        const bool aff = (abin != 0);
        const float4* x4 = gat ? 0 : ((const float4*)x + (size_t)blk*(128*32));
        const float4* f4 = (const float4*)feat2;
        #pragma unroll
        for (int i = 0; i < 16; i++){
            const int f = t + i*256;
            const int row = f >> 5, c4 = f & 31;
            float4 v;
            if (gat){
                const int4   id = iqp[blk*128 + row];
                const float4 w  = wqp[blk*128 + row];
                const float4 a = f4[id.x*32 + c4];
                const float4 b = f4[id.y*32 + c4];
                const float4 c = f4[id.z*32 + c4];
                v.x = a.x*w.x + b.x*w.y + c.x*w.z;
                v.y = a.y*w.x + b.y*w.y + c.y*w.z;
                v.z = a.z*w.x + b.z*w.y + c.z*w.z;
                v.w = a.w*w.x + b.w*w.y + c.w*w.z;
            } else {
                v = x4[f];
                if (aff){
                    const float4 sc = ((const float4*)abin)[c4];
                    const float4 sf = ((const float4*)abin)[32 + c4];
                    v.x = fmaxf(fmaf(v.x, sc.x, sf.x), 0.f);
                    v.y = fmaxf(fmaf(v.y, sc.y, sf.y), 0.f);
                    v.z = fmaxf(fmaf(v.z, sc.z, sf.z), 0.f);
                    v.w = fmaxf(fmaf(v.w, sc.w, sf.w), 0.f);
                }
            }
            const __nv_bfloat16 h0 = __float2bfloat16(v.x), h1 = __float2bfloat16(v.y);
            const __nv_bfloat16 h2 = __float2bfloat16(v.z), h3 = __float2bfloat16(v.w);
            const __nv_bfloat16 l0 = __float2bfloat16(v.x - __bfloat162float(h0));
            const __nv_bfloat16 l1 = __float2bfloat16(v.y - __bfloat162float(h1));
            const __nv_bfloat16 l2 = __float2bfloat16(v.z - __bfloat162float(h2));
            const __nv_bfloat16 l3 = __float2bfloat16(v.w - __bfloat162float(h3));
            const unsigned off = (unsigned)(row*(RSTR*2) + c4*8);
            *(uint2*)(s_raw + O_AHI + off) = make_uint2(pkbf(h0,h1), pkbf(h2,h3));
            *(uint2*)(s_raw + O_ALO + off) = make_uint2(pkbf(l0,l1), pkbf(l2,l3));
        }
    }
    {
        #pragma unroll
        for (int i = 0; i < 16; i++){
            const int u = t + i*256;
            const int row = u >> 5, c4 = u & 31;
            const unsigned off = (unsigned)(row*(RSTR*2) + c4*8);
            *(uint2*)(s_raw + O_BHI + off) = *(const uint2*)(whi + row*128 + c4*4);
            *(uint2*)(s_raw + O_BLO + off) = *(const uint2*)(wlo + row*128 + c4*4);
        }
    }
    __syncthreads();

    const unsigned aRowOff = (unsigned)((wm*32 + (lane & 15))*(RSTR*2) + (lane >> 4)*16);
    const unsigned bRowOff = (unsigned)((wn*64 + (lane & 7) + ((lane >> 4) << 3))*(RSTR*2)
                                        + ((lane & 8) ? 16 : 0));

    float acc[2][8][4];
    #pragma unroll
    for (int mi = 0; mi < 2; mi++)
        #pragma unroll
        for (int ni = 0; ni < 8; ni++)
            #pragma unroll
            for (int q = 0; q < 4; q++) acc[mi][ni][q] = 0.f;

    #pragma unroll
    for (int ph = 0; ph < 3; ph++){
        const unsigned abuf = sb + ((ph == 2) ? O_ALO : O_AHI);
        const unsigned bbuf = sb + ((ph == 1) ? O_BLO : O_BHI);
        #pragma unroll
        for (int k0 = 0; k0 < 8; k0++){
            unsigned a0[4], a1[4];
            LDSM_X4(a0, abuf + aRowOff + k0*32);
            LDSM_X4(a1, abuf + aRowOff + 16*(RSTR*2) + k0*32);
            #pragma unroll
            for (int n2 = 0; n2 < 4; n2++){
                unsigned bf[4];
                LDSM_X4(bf, bbuf + bRowOff + n2*16*(RSTR*2) + k0*32);
                MMA16816(acc[0][n2*2],   a0, bf[0], bf[1]);
                MMA16816(acc[0][n2*2+1], a0, bf[2], bf[3]);
                MMA16816(acc[1][n2*2],   a1, bf[0], bf[1]);
                MMA16816(acc[1][n2*2+1], a1, bf[2], bf[3]);
            }
        }
    }

    const int qrow = lane >> 2;
    const int qcol = (lane & 3)*2;
    #pragma unroll
    for (int ni = 0; ni < 8; ni++){
        const int col = wn*64 + ni*8 + qcol;
        const float b0 = __ldg(&bias[col]);
        const float b1 = __ldg(&bias[col+1]);
        float s0 = 0.f, s1 = 0.f, q0 = 0.f, q1 = 0.f;
        #pragma unroll
        for (int mi = 0; mi < 2; mi++){
            const int row = blk*128 + wm*32 + mi*16 + qrow;
            const float v0 = acc[mi][ni][0] + b0;
            const float v1 = acc[mi][ni][1] + b1;
            const float v2 = acc[mi][ni][2] + b0;
            const float v3 = acc[mi][ni][3] + b1;
            *(float2*)(y + (size_t)row*128 + col)       = make_float2(v0, v1);
            *(float2*)(y + (size_t)(row + 8)*128 + col) = make_float2(v2, v3);
            s0 += v0 + v2; s1 += v1 + v3;
            q0 += v0*v0 + v2*v2; q1 += v1*v1 + v3*v3;
        }
        #pragma unroll
        for (int d = 4; d < 32; d <<= 1){
            s0 += __shfl_xor_sync(0xffffffffu, s0, d);
            s1 += __shfl_xor_sync(0xffffffffu, s1, d);
            q0 += __shfl_xor_sync(0xffffffffu, q0, d);
            q1 += __shfl_xor_sync(0xffffffffu, q1, d);
        }
        if (lane < 4){
            atomicAdd(&ssum[col], s0);
            atomicAdd(&ssum[col+1], s1);
            atomicAdd(&ssq[col], q0);
            atomicAdd(&ssq[col+1], q1);
        }
    }
    __syncthreads();
    if (t < 128){
        atomicAdd(&gs[t], ssum[t]);
        atomicAdd(&gq[t], ssq[t]);
    }
    __threadfence();
    __syncthreads();
    __shared__ unsigned s_last;
    if (t == 0){
        const unsigned v = atomicInc(ctr, 255);   // grid=256
        s_last = (v == 255) ? 1u : 0u;
    }
    __syncthreads();
    if (s_last && t < 128){
        const float ss = atomicAdd(&gs[t], 0.f);
        const float qq = atomicAdd(&gq[t], 0.f);
        const float m  = ss * (1.f/32768.f);
        const float vv = qq * (1.f/32768.f) - m*m;
        const float sc = g[t] * rsqrtf(vv + 1e-5f);
        about[t]       = sc;
        about[128 + t] = be[t] - m*sc;
        gs[t] = 0.f;
        gq[t] = 0.f;
    }
}

// ---------------- final BN+ReLU to output ----------------
__global__ void __launch_bounds__(256,1) final_kernel(const float4* __restrict__ y,
                                                      const float* __restrict__ ab,
                                                      float4* __restrict__ out)
{
    const int i = blockIdx.x*256 + threadIdx.x;
    const int c = i & 31;
    const float4 sc = ((const float4*)ab)[c];
    const float4 sf = ((const float4*)ab)[32 + c];
    const float4 v = y[i];
    float4 o;
    o.x = fmaxf(fmaf(v.x, sc.x, sf.x), 0.f);
    o.y = fmaxf(fmaf(v.y, sc.y, sf.y), 0.f);
    o.z = fmaxf(fmaf(v.z, sc.z, sf.z), 0.f);
    o.w = fmaxf(fmaf(v.w, sc.w, sf.w), 0.f);
    out[i] = o;
}

// ---------------- launch ----------------
extern "C" void kernel_launch(void* const* d_in, const int* in_sizes, int n_in,
                              void* d_out, int out_size)
{
    const float* pos1  = (const float*)d_in[0];
    const float* pos2  = (const float*)d_in[1];
    const float* feat2 = (const float*)d_in[2];
    const float* Wm[3]  = {(const float*)d_in[3],  (const float*)d_in[7],  (const float*)d_in[11]};
    const float* bm[3]  = {(const float*)d_in[4],  (const float*)d_in[8],  (const float*)d_in[12]};
    const float* gm[3]  = {(const float*)d_in[5],  (const float*)d_in[9],  (const float*)d_in[13]};
    const float* bem[3] = {(const float*)d_in[6],  (const float*)d_in[10], (const float*)d_in[14]};

    float4 *wq, *pdist; int4 *iq, *pidx; float *x0, *ya, *yb, *gs, *gq, *ab;
    __nv_bfloat16 *whi, *wlo;
    unsigned* ctr;
    cudaGetSymbolAddress((void**)&wq, g_wq);
    cudaGetSymbolAddress((void**)&iq, g_iq);
    cudaGetSymbolAddress((void**)&pdist, g_pd);
    cudaGetSymbolAddress((void**)&pidx, g_pi);
    cudaGetSymbolAddress((void**)&x0, g_x0);
    cudaGetSymbolAddress((void**)&ya, g_ya);
    cudaGetSymbolAddress((void**)&yb, g_yb);
    cudaGetSymbolAddress((void**)&whi, g_whi);
    cudaGetSymbolAddress((void**)&wlo, g_wlo);
    cudaGetSymbolAddress((void**)&gs, g_sum);
    cudaGetSymbolAddress((void**)&gq, g_sq);
    cudaGetSymbolAddress((void**)&ctr, g_ctr);
    cudaGetSymbolAddress((void**)&ab, g_ab);

    cudaFuncSetAttribute(gemm_tc_kernel, cudaFuncAttributeMaxDynamicSharedMemorySize, GEMM_SMEM);

    prep_w_kernel<<<192,256>>>(Wm[0], Wm[1], Wm[2], whi, wlo);

    knn_part_kernel<<<(Nq/KQB)*NCH, KTPB>>>(pos1, pos2, pdist, pidx);
    knn_merge_kernel<<<Nq/256, 256>>>(pos1, pdist, pidx, wq, iq);

    // layer 1 fuses the interpolation gather (x = null)
    gemm_tc_kernel<<<256,256,GEMM_SMEM>>>(0,  wq, iq, feat2, whi,         wlo,         bm[0], 0,  gm[0], bem[0], ya, gs, gq, ctr, ab);
    gemm_tc_kernel<<<256,256,GEMM_SMEM>>>(ya, 0,  0,  0,     whi + 16384, wlo + 16384, bm[1], ab, gm[1], bem[1], yb, gs, gq, ctr, ab);
    gemm_tc_kernel<<<256,256,GEMM_SMEM>>>(yb, 0,  0,  0,     whi + 32768, wlo + 32768, bm[2], ab, gm[2], bem[2], x0, gs, gq, ctr, ab);
    final_kernel<<<4096,256>>>((const float4*)x0, ab, (float4*)d_out);
}

// round 17
// speedup vs baseline: 1.3086x; 1.0080x over previous
#include <cuda_runtime.h>
#include <cuda_bf16.h>

#define Nq 32768
#define Mp 8192
#define C  128

// ---- knn config (R6/R13-proven) ----
#define KTPB 128
#define KQB  128
#define NCH  4
#define KHALF (Mp/NCH)
#define SUB  512
#define NSUB (KHALF/2/SUB)

typedef unsigned long long ull;

union F2U { float2 f; ull u; };
__device__ __forceinline__ ull pk2(float a, float b){ F2U t; t.f.x=a; t.f.y=b; return t.u; }
__device__ __forceinline__ float lo2(ull v){ F2U t; t.u=v; return t.f.x; }
__device__ __forceinline__ float hi2(ull v){ F2U t; t.u=v; return t.f.y; }
__device__ __forceinline__ ull fma2(ull a, ull b, ull c){
    ull d; asm("fma.rn.f32x2 %0, %1, %2, %3;" : "=l"(d) : "l"(a), "l"(b), "l"(c)); return d;
}

// branchless stable top-3 insert (strict < => ties keep earlier-seen/lower index)
__device__ __forceinline__ void ins3(float t, int idx,
                                     float& d0, float& d1, float& d2,
                                     int& i0, int& i1, int& i2)
{
    const bool c0 = t < d0, c1 = t < d1, c2 = t < d2;
    d2 = c1 ? d1 : (c2 ? t : d2);
    i2 = c1 ? i1 : (c2 ? idx : i2);
    d1 = c0 ? d0 : (c1 ? t : d1);
    i1 = c0 ? i0 : (c1 ? idx : i1);
    d0 = c0 ? t : d0;
    i0 = c0 ? idx : i0;
}

__device__ __forceinline__ unsigned smem_to_u32(const void* p){
    unsigned a;
    asm("{ .reg .u64 tmp; cvta.to.shared.u64 tmp, %1; cvt.u32.u64 %0, tmp; }" : "=r"(a) : "l"(p));
    return a;
}

#define LDSM_X4(r, addr) \
    asm volatile("ldmatrix.sync.aligned.m8n8.x4.shared.b16 {%0,%1,%2,%3}, [%4];" \
        : "=r"((r)[0]),"=r"((r)[1]),"=r"((r)[2]),"=r"((r)[3]) : "r"(addr))

#define MMA16816(d, a, b0_, b1_) \
    asm volatile("mma.sync.aligned.m16n8k16.row.col.f32.bf16.bf16.f32 " \
        "{%0,%1,%2,%3}, {%4,%5,%6,%7}, {%8,%9}, {%0,%1,%2,%3};" \
        : "+f"((d)[0]),"+f"((d)[1]),"+f"((d)[2]),"+f"((d)[3]) \
        : "r"((a)[0]),"r"((a)[1]),"r"((a)[2]),"r"((a)[3]), "r"(b0_),"r"(b1_))

// ---------------- scratch (device globals; no allocs allowed) ----------------
__device__ float4 g_wq[Nq];
__device__ int4   g_iq[Nq];
__device__ float4 g_pd[NCH*Nq];
__device__ int4   g_pi[NCH*Nq];
__device__ float  g_x0[Nq*C];
__device__ float  g_ya[Nq*C];
__device__ float  g_yb[Nq*C];
__device__ __nv_bfloat16 g_whi[3*C*C];
__device__ __nv_bfloat16 g_wlo[3*C*C];
__device__ float  g_sum[C];
__device__ float  g_sq[C];
__device__ unsigned g_ctr;
__device__ float  g_ab[2*C];

extern __shared__ unsigned char s_raw[];

// ---------------- W -> bf16 hi/lo (once) ----------------
__global__ void __launch_bounds__(256,1) prep_w_kernel(const float* __restrict__ w0,
                                                       const float* __restrict__ w1,
                                                       const float* __restrict__ w2,
                                                       __nv_bfloat16* __restrict__ whi,
                                                       __nv_bfloat16* __restrict__ wlo)
{
    const int b = blockIdx.x;                   // 192 blocks
    const float* w = (b < 64) ? w0 : ((b < 128) ? w1 : w2);
    const int local = (b & 63)*256 + threadIdx.x;
    const int gi = (b >> 6)*16384 + local;
    const float v = w[local];
    const __nv_bfloat16 hi = __float2bfloat16(v);
    whi[gi] = hi;
    wlo[gi] = __float2bfloat16(v - __bfloat162float(hi));
}

// -------- kNN partial (R6-proven; split guards) --------
__global__ void __launch_bounds__(KTPB,8) knn_part_kernel(const float* __restrict__ pos1,
                                                          const float* __restrict__ pos2,
                                                          float4* __restrict__ pd,
                                                          int4*  __restrict__ pi)
{
    __shared__ ulonglong2 sA[SUB];
    __shared__ ulonglong2 sB[SUB];
    const int t     = threadIdx.x;
    const int chunk = blockIdx.x & (NCH-1);
    const int n     = (blockIdx.x >> 2) * KQB + t;

    const float px = pos1[3*n], py = pos1[3*n+1], pz = pos1[3*n+2];
    const ull pxx = pk2(px,px), pyy = pk2(py,py), pzz = pk2(pz,pz);

    float d0=3.4e38f, d1=3.4e38f, d2=3.4e38f;
    int   i0=0, i1=0, i2=0;

    const int pb0 = chunk * (KHALF/2);

    for (int sc = 0; sc < NSUB; sc++){
        const int pb = pb0 + sc*SUB;
        __syncthreads();
        #pragma unroll
        for (int i = 0; i < SUB/KTPB; i++){
            const int p = t + i*KTPB;
            const float2* q2 = (const float2*)(pos2 + 6*(pb + p));
            const float2 a = q2[0], b = q2[1], c = q2[2];
            const float x0=a.x, y0=a.y, z0=b.x, x1=b.y, y1=c.x, z1=c.y;
            const float n0 = x0*x0 + y0*y0 + z0*z0;
            const float n1 = x1*x1 + y1*y1 + z1*z1;
            ulonglong2 A, B;
            A.x = pk2(-2.f*x0, -2.f*x1);
            A.y = pk2(-2.f*y0, -2.f*y1);
            B.x = pk2(-2.f*z0, -2.f*z1);
            B.y = pk2(n0, n1);
            sA[p] = A; sB[p] = B;
        }
        __syncthreads();

        #pragma unroll 4
        for (int p = 0; p < SUB; p++){
            const ulonglong2 A = sA[p];
            const ulonglong2 B = sB[p];
            ull tt = fma2(pzz, B.x, B.y);
            tt = fma2(pyy, A.y, tt);
            tt = fma2(pxx, A.x, tt);
            const float tl = lo2(tt), th = hi2(tt);
            const int g = 2*(pb + p);
            if (tl < d2) ins3(tl, g,   d0, d1, d2, i0, i1, i2);
            if (th < d2) ins3(th, g+1, d0, d1, d2, i0, i1, i2);
        }
    }

    pd[chunk*Nq + n] = make_float4(d0, d1, d2, 0.f);
    pi[chunk*Nq + n] = make_int4(i0, i1, i2, 0);
}

// ---------------- merge partials -> weights/indices (R6) ----------------
__global__ void __launch_bounds__(256,1) knn_merge_kernel(const float* __restrict__ pos1,
                                                          const float4* __restrict__ pd,
                                                          const int4*  __restrict__ pi,
                                                          float4* __restrict__ wq,
                                                          int4*  __restrict__ iq)
{
    const int n = blockIdx.x*256 + threadIdx.x;
    float4 v = pd[n];
    int4  id = pi[n];
    float d0=v.x, d1=v.y, d2=v.z;
    int   i0=id.x, i1=id.y, i2=id.z;

    #pragma unroll
    for (int c = 1; c < NCH; c++){
        const float4 e = pd[c*Nq + n];
        const int4   j = pi[c*Nq + n];
        ins3(e.x, j.x, d0, d1, d2, i0, i1, i2);
        ins3(e.y, j.y, d0, d1, d2, i0, i1, i2);
        ins3(e.z, j.z, d0, d1, d2, i0, i1, i2);
    }

    const float px = pos1[3*n], py = pos1[3*n+1], pz = pos1[3*n+2];
    const float n1 = px*px + py*py + pz*pz;
    const float a0 = fmaxf(d0 + n1, 0.f) + 1e-8f;
    const float a1 = fmaxf(d1 + n1, 0.f) + 1e-8f;
    const float a2 = fmaxf(d2 + n1, 0.f) + 1e-8f;
    const float w0 = 1.f/a0, w1 = 1.f/a1, w2 = 1.f/a2;
    const float inv = 1.f/(w0 + w1 + w2);
    wq[n] = make_float4(w0*inv, w1*inv, w2*inv, 0.f);
    iq[n] = make_int4(i0, i1, i2, 0);
}

// ---------------- mma.sync split-bf16 GEMM + fused BN epilogue -------------
// 512 threads / 16 warps (warp tile 32x32) for 2x latency hiding.
// Layer 1 fuses the kNN interpolation gather into the X-stage.
#define RSTR 136
#define TILE_B (128*RSTR*2)
#define O_AHI 0
#define O_ALO (TILE_B)
#define O_BHI (2*TILE_B)
#define O_BLO (3*TILE_B)
#define O_CTL (4*TILE_B)
#define GEMM_SMEM (O_CTL + 1024)

__device__ __forceinline__ unsigned pkbf(__nv_bfloat16 a, __nv_bfloat16 b){
    __nv_bfloat162 h; h.x = a; h.y = b;
    return *(unsigned*)&h;
}

__global__ void __launch_bounds__(512,1)
gemm_tc_kernel(const float* __restrict__ x,          // null for layer 1 (gather path)
               const float4* __restrict__ wqp,       // layer-1 gather inputs
               const int4*  __restrict__ iqp,
               const float* __restrict__ feat2,
               const __nv_bfloat16* __restrict__ whi,
               const __nv_bfloat16* __restrict__ wlo,
               const float* __restrict__ bias,
               const float* __restrict__ abin,       // prev scale|shift or null
               const float* __restrict__ g,
               const float* __restrict__ be,
               float* __restrict__ y,
               float* __restrict__ gs,
               float* __restrict__ gq,
               unsigned* __restrict__ ctr,
               float* __restrict__ about)
{
    const unsigned sb = smem_to_u32(s_raw);
    const int t    = threadIdx.x;
    const int wid  = t >> 5, lane = t & 31;
    const int wm   = wid & 3;            // m block: wm*32
    const int wn   = wid >> 2;           // n block: wn*32
    const int blk  = blockIdx.x;
    float* ssum = (float*)(s_raw + O_CTL);
    float* ssq  = (float*)(s_raw + O_CTL + 512);

    if (t < 128){ ssum[t] = 0.f; ssq[t] = 0.f; }

    { // stage X tile -> bf16 hi/lo; layer1: gather interp inline; else affine+relu
        const bool gat = (x == 0);
        const bool aff = (abin != 0);
        const float4* x4 = gat ? 0 : ((const float4*)x + (size_t)blk*(128*32));
        const float4* f4 = (const float4*)feat2;
        #pragma unroll
        for (int i = 0; i < 8; i++){
            const int f = t + i*512;
            const int row = f >> 5, c4 = f & 31;
            float4 v;
            if (gat){
                const int4   id = iqp[blk*128 + row];
                const float4 w  = wqp[blk*128 + row];
                const float4 a = f4[id.x*32 + c4];
                const float4 b = f4[id.y*32 + c4];
                const float4 c = f4[id.z*32 + c4];
                v.x = a.x*w.x + b.x*w.y + c.x*w.z;
                v.y = a.y*w.x + b.y*w.y + c.y*w.z;
                v.z = a.z*w.x + b.z*w.y + c.z*w.z;
                v.w = a.w*w.x + b.w*w.y + c.w*w.z;
            } else {
                v = x4[f];
                if (aff){
                    const float4 sc = ((const float4*)abin)[c4];
                    const float4 sf = ((const float4*)abin)[32 + c4];
                    v.x = fmaxf(fmaf(v.x, sc.x, sf.x), 0.f);
                    v.y = fmaxf(fmaf(v.y, sc.y, sf.y), 0.f);
                    v.z = fmaxf(fmaf(v.z, sc.z, sf.z), 0.f);
                    v.w = fmaxf(fmaf(v.w, sc.w, sf.w), 0.f);
                }
            }
            const __nv_bfloat16 h0 = __float2bfloat16(v.x), h1 = __float2bfloat16(v.y);
            const __nv_bfloat16 h2 = __float2bfloat16(v.z), h3 = __float2bfloat16(v.w);
            const __nv_bfloat16 l0 = __float2bfloat16(v.x - __bfloat162float(h0));
            const __nv_bfloat16 l1 = __float2bfloat16(v.y - __bfloat162float(h1));
            const __nv_bfloat16 l2 = __float2bfloat16(v.z - __bfloat162float(h2));
            const __nv_bfloat16 l3 = __float2bfloat16(v.w - __bfloat162float(h3));
            const unsigned off = (unsigned)(row*(RSTR*2) + c4*8);
            *(uint2*)(s_raw + O_AHI + off) = make_uint2(pkbf(h0,h1), pkbf(h2,h3));
            *(uint2*)(s_raw + O_ALO + off) = make_uint2(pkbf(l0,l1), pkbf(l2,l3));
        }
    }
    {
        #pragma unroll
        for (int i = 0; i < 8; i++){
            const int u = t + i*512;
            const int row = u >> 5, c4 = u & 31;
            const unsigned off = (unsigned)(row*(RSTR*2) + c4*8);
            *(uint2*)(s_raw + O_BHI + off) = *(const uint2*)(whi + row*128 + c4*4);
            *(uint2*)(s_raw + O_BLO + off) = *(const uint2*)(wlo + row*128 + c4*4);
        }
    }
    __syncthreads();

    const unsigned aRowOff = (unsigned)((wm*32 + (lane & 15))*(RSTR*2) + (lane >> 4)*16);
    const unsigned bRowOff = (unsigned)((wn*32 + (lane & 7) + ((lane >> 4) << 3))*(RSTR*2)
                                        + ((lane & 8) ? 16 : 0));

    float acc[2][4][4];
    #pragma unroll
    for (int mi = 0; mi < 2; mi++)
        #pragma unroll
        for (int ni = 0; ni < 4; ni++)
            #pragma unroll
            for (int q = 0; q < 4; q++) acc[mi][ni][q] = 0.f;

    #pragma unroll
    for (int ph = 0; ph < 3; ph++){
        const unsigned abuf = sb + ((ph == 2) ? O_ALO : O_AHI);
        const unsigned bbuf = sb + ((ph == 1) ? O_BLO : O_BHI);
        #pragma unroll
        for (int k0 = 0; k0 < 8; k0++){
            unsigned a0[4], a1[4];
            LDSM_X4(a0, abuf + aRowOff + k0*32);
            LDSM_X4(a1, abuf + aRowOff + 16*(RSTR*2) + k0*32);
            #pragma unroll
            for (int n2 = 0; n2 < 2; n2++){
                unsigned bf[4];
                LDSM_X4(bf, bbuf + bRowOff + n2*16*(RSTR*2) + k0*32);
                MMA16816(acc[0][n2*2],   a0, bf[0], bf[1]);
                MMA16816(acc[0][n2*2+1], a0, bf[2], bf[3]);
                MMA16816(acc[1][n2*2],   a1, bf[0], bf[1]);
                MMA16816(acc[1][n2*2+1], a1, bf[2], bf[3]);
            }
        }
    }

    const int qrow = lane >> 2;
    const int qcol = (lane & 3)*2;
    #pragma unroll
    for (int ni = 0; ni < 4; ni++){
        const int col = wn*32 + ni*8 + qcol;
        const float b0 = __ldg(&bias[col]);
        const float b1 = __ldg(&bias[col+1]);
        float s0 = 0.f, s1 = 0.f, q0 = 0.f, q1 = 0.f;
        #pragma unroll
        for (int mi = 0; mi < 2; mi++){
            const int row = blk*128 + wm*32 + mi*16 + qrow;
            const float v0 = acc[mi][ni][0] + b0;
            const float v1 = acc[mi][ni][1] + b1;
            const float v2 = acc[mi][ni][2] + b0;
            const float v3 = acc[mi][ni][3] + b1;
            *(float2*)(y + (size_t)row*128 + col)       = make_float2(v0, v1);
            *(float2*)(y + (size_t)(row + 8)*128 + col) = make_float2(v2, v3);
            s0 += v0 + v2; s1 += v1 + v3;
            q0 += v0*v0 + v2*v2; q1 += v1*v1 + v3*v3;
        }
        #pragma unroll
        for (int d = 4; d < 32; d <<= 1){
            s0 += __shfl_xor_sync(0xffffffffu, s0, d);
            s1 += __shfl_xor_sync(0xffffffffu, s1, d);
            q0 += __shfl_xor_sync(0xffffffffu, q0, d);
            q1 += __shfl_xor_sync(0xffffffffu, q1, d);
        }
        if (lane < 4){
            atomicAdd(&ssum[col], s0);
            atomicAdd(&ssum[col+1], s1);
            atomicAdd(&ssq[col], q0);
            atomicAdd(&ssq[col+1], q1);
        }
    }
    __syncthreads();
    if (t < 128){
        atomicAdd(&gs[t], ssum[t]);
        atomicAdd(&gq[t], ssq[t]);
    }
    __threadfence();
    __syncthreads();
    __shared__ unsigned s_last;
    if (t == 0){
        const unsigned v = atomicInc(ctr, 255);   // grid=256
        s_last = (v == 255) ? 1u : 0u;
    }
    __syncthreads();
    if (s_last && t < 128){
        const float ss = atomicAdd(&gs[t], 0.f);
        const float qq = atomicAdd(&gq[t], 0.f);
        const float m  = ss * (1.f/32768.f);
        const float vv = qq * (1.f/32768.f) - m*m;
        const float sc = g[t] * rsqrtf(vv + 1e-5f);
        about[t]       = sc;
        about[128 + t] = be[t] - m*sc;
        gs[t] = 0.f;
        gq[t] = 0.f;
    }
}

// ---------------- final BN+ReLU to output ----------------
__global__ void __launch_bounds__(256,1) final_kernel(const float4* __restrict__ y,
                                                      const float* __restrict__ ab,
                                                      float4* __restrict__ out)
{
    const int i = blockIdx.x*256 + threadIdx.x;
    const int c = i & 31;
    const float4 sc = ((const float4*)ab)[c];
    const float4 sf = ((const float4*)ab)[32 + c];
    const float4 v = y[i];
    float4 o;
    o.x = fmaxf(fmaf(v.x, sc.x, sf.x), 0.f);
    o.y = fmaxf(fmaf(v.y, sc.y, sf.y), 0.f);
    o.z = fmaxf(fmaf(v.z, sc.z, sf.z), 0.f);
    o.w = fmaxf(fmaf(v.w, sc.w, sf.w), 0.f);
    out[i] = o;
}

// ---------------- launch ----------------
extern "C" void kernel_launch(void* const* d_in, const int* in_sizes, int n_in,
                              void* d_out, int out_size)
{
    const float* pos1  = (const float*)d_in[0];
    const float* pos2  = (const float*)d_in[1];
    const float* feat2 = (const float*)d_in[2];
    const float* Wm[3]  = {(const float*)d_in[3],  (const float*)d_in[7],  (const float*)d_in[11]};
    const float* bm[3]  = {(const float*)d_in[4],  (const float*)d_in[8],  (const float*)d_in[12]};
    const float* gm[3]  = {(const float*)d_in[5],  (const float*)d_in[9],  (const float*)d_in[13]};
    const float* bem[3] = {(const float*)d_in[6],  (const float*)d_in[10], (const float*)d_in[14]};

    float4 *wq, *pdist; int4 *iq, *pidx; float *x0, *ya, *yb, *gs, *gq, *ab;
    __nv_bfloat16 *whi, *wlo;
    unsigned* ctr;
    cudaGetSymbolAddress((void**)&wq, g_wq);
    cudaGetSymbolAddress((void**)&iq, g_iq);
    cudaGetSymbolAddress((void**)&pdist, g_pd);
    cudaGetSymbolAddress((void**)&pidx, g_pi);
    cudaGetSymbolAddress((void**)&x0, g_x0);
    cudaGetSymbolAddress((void**)&ya, g_ya);
    cudaGetSymbolAddress((void**)&yb, g_yb);
    cudaGetSymbolAddress((void**)&whi, g_whi);
    cudaGetSymbolAddress((void**)&wlo, g_wlo);
    cudaGetSymbolAddress((void**)&gs, g_sum);
    cudaGetSymbolAddress((void**)&gq, g_sq);
    cudaGetSymbolAddress((void**)&ctr, g_ctr);
    cudaGetSymbolAddress((void**)&ab, g_ab);

    cudaFuncSetAttribute(gemm_tc_kernel, cudaFuncAttributeMaxDynamicSharedMemorySize, GEMM_SMEM);

    prep_w_kernel<<<192,256>>>(Wm[0], Wm[1], Wm[2], whi, wlo);

    knn_part_kernel<<<(Nq/KQB)*NCH, KTPB>>>(pos1, pos2, pdist, pidx);
    knn_merge_kernel<<<Nq/256, 256>>>(pos1, pdist, pidx, wq, iq);

    // layer 1 fuses the interpolation gather (x = null)
    gemm_tc_kernel<<<256,512,GEMM_SMEM>>>(0,  wq, iq, feat2, whi,         wlo,         bm[0], 0,  gm[0], bem[0], ya, gs, gq, ctr, ab);
    gemm_tc_kernel<<<256,512,GEMM_SMEM>>>(ya, 0,  0,  0,     whi + 16384, wlo + 16384, bm[1], ab, gm[1], bem[1], yb, gs, gq, ctr, ab);
    gemm_tc_kernel<<<256,512,GEMM_SMEM>>>(yb, 0,  0,  0,     whi + 32768, wlo + 32768, bm[2], ab, gm[2], bem[2], x0, gs, gq, ctr, ab);
    final_kernel<<<4096,256>>>((const float4*)x0, ab, (float4*)d_out);
}